// round 17
// baseline (speedup 1.0000x reference)
#include <cuda_runtime.h>
#include <cstdint>
#include <cstddef>

#define IN_F   8192
#define OUT_F  8192
#define BATCH  32
#define KSPLIT 8
#define KCHUNK (IN_F / KSPLIT)     // 1024 ints per CTA
#define NIT    (KCHUNK / 32)       // 32 k32 steps per CTA
#define MTILE  64                  // rows per CTA (4 warps x 16 rows)
#define THREADS 128
#define NMT    (OUT_F / MTILE)     // 128 m-tiles
#define NS32   (IN_F / 32)         // 256 global k32 steps
#define NK4    (IN_F / 4)          // 2048 global k4 groups

#define S0 0.0625f                 // 2^-4
#define S1 0.00048828125f          // 2^-11

// hi plane (q0), frag order j=0..3: u2 idx (s*4+j)*32 + g*4 + t
__device__ uint32_t g_xbq[(size_t)NS32 * 128 * 2];               // 256 KB
// lo plane (q1) b=0..23, frag order j=0..2: u2 idx (s*3+j)*32 + g*4 + t
__device__ uint32_t g_xlq[(size_t)NS32 * 96 * 2];                // 192 KB
// lo plane (q1) b=24..31 as [k4_global][b-24]
__device__ uint32_t g_xlo[(size_t)NK4 * 8];                      // 64 KB
__device__ float g_partial[(size_t)KSPLIT * OUT_F * BATCH];      // 8 MB
__device__ int   g_cnt[NMT];

// ---- helpers -----------------------------------------------------------------
__device__ __forceinline__ uint32_t prmt(uint32_t a, uint32_t b, uint32_t sel) {
    uint32_t d;
    asm("prmt.b32 %0, %1, %2, %3;" : "=r"(d) : "r"(a), "r"(b), "r"(sel));
    return d;
}
__device__ __forceinline__ uint32_t pack_s8(int4 w) {
    uint32_t lo = prmt((uint32_t)w.x, (uint32_t)w.y, 0x0040);
    uint32_t hi = prmt((uint32_t)w.z, (uint32_t)w.w, 0x0040);
    return prmt(lo, hi, 0x5410);
}
__device__ __forceinline__ void imma16832(int* d, uint32_t a0, uint32_t a1,
                                          uint32_t a2, uint32_t a3,
                                          uint32_t b0, uint32_t b1) {
    asm volatile(
        "mma.sync.aligned.m16n8k32.row.col.s32.s8.s8.s32 "
        "{%0,%1,%2,%3}, {%4,%5,%6,%7}, {%8,%9}, {%0,%1,%2,%3};"
        : "+r"(d[0]), "+r"(d[1]), "+r"(d[2]), "+r"(d[3])
        : "r"(a0), "r"(a1), "r"(a2), "r"(a3), "r"(b0), "r"(b1));
}
__device__ __forceinline__ int dp4a_(uint32_t a, uint32_t b, int c) {
    int d;
    asm("dp4a.s32.s32 %0, %1, %2, %3;" : "=r"(d) : "r"(a), "r"(b), "r"(c));
    return d;
}
__device__ __forceinline__ int q8(float v, float mul, float lim) {
    float q = rintf(v * mul);
    q = fminf(fmaxf(q, -lim), lim);
    return (int)q;
}

// ---- Kernel 1: x -> hi frag, lo frag (b<24), lo scalar (b>=24); zero counters -
__global__ void xprep_kernel(const float* __restrict__ x) {
    int gidx = blockIdx.x * blockDim.x + threadIdx.x;   // 65536 threads
    if (blockIdx.x == 0 && threadIdx.x < NMT) g_cnt[threadIdx.x] = 0;

    int b  = gidx >> 11;
    int k4 = gidx & 2047;
    int k0 = k4 * 4;
    float4 v = ((const float4*)(x + (size_t)b * IN_F))[k4];

    int q0[4], q1[4];
    float xs[4] = {v.x, v.y, v.z, v.w};
#pragma unroll
    for (int i = 0; i < 4; i++) {
        q0[i] = q8(xs[i], 16.0f, 127.0f);
        float r = xs[i] - (float)q0[i] * S0;
        q1[i] = q8(r, 2048.0f, 127.0f);
    }
    uint32_t p0 = (uint32_t)(q0[0] & 0xFF) | ((uint32_t)(q0[1] & 0xFF) << 8) |
                  ((uint32_t)(q0[2] & 0xFF) << 16) | ((uint32_t)(q0[3] & 0xFF) << 24);
    uint32_t p1 = (uint32_t)(q1[0] & 0xFF) | ((uint32_t)(q1[1] & 0xFF) << 8) |
                  ((uint32_t)(q1[2] & 0xFF) << 16) | ((uint32_t)(q1[3] & 0xFF) << 24);

    int s = k0 >> 5;
    int q = k0 & 31;
    int t = (q & 15) >> 2;
    int h = q >> 4;
    int j0 = b >> 3, g0 = b & 7;

    g_xbq[((size_t)(s * 4 + j0) * 32 + g0 * 4 + t) * 2 + h] = p0;

    if (b < 24) {
        g_xlq[((size_t)(s * 3 + j0) * 32 + g0 * 4 + t) * 2 + h] = p1;
    } else {
        g_xlo[(size_t)k4 * 8 + (b - 24)] = p1;
    }
}

// ---- Kernel 2: 7 IMMA (hi + lo b<24) + shuffle-free dp4a (lo b>=24) ----------
// dp4a uses k-ownership: each thread multiplies its OWN weight words against
// all 8 b-columns, k-partial; one quad shfl_xor reduction at the end.
__global__ void __launch_bounds__(THREADS, 4)
gemm_kernel(const int* __restrict__ W,
            const float* __restrict__ log_scale,
            const float* __restrict__ bias,
            float* __restrict__ out) {
    __shared__ uint32_t sxlo[(KCHUNK / 4) * 8];         // 8 KB: [k4_local][b-24]

    const int tid  = threadIdx.x;
    const int lane = tid & 31;
    const int warp = tid >> 5;                          // 0..3
    const int g    = lane >> 2;                         // 0..7
    const int t    = lane & 3;                          // 0..3

    const int mt      = blockIdx.x;
    const int rowbase = mt * MTILE;
    const int kbase   = blockIdx.y * KCHUNK;
    const int sbase   = kbase >> 5;

    // Stage dp4a lo slice (contiguous 8 KB of g_xlo), coalesced.
    {
        const uint4* __restrict__ src =
            (const uint4*)(g_xlo + (size_t)(kbase >> 2) * 8);
        uint4* dst = (uint4*)sxlo;
#pragma unroll
        for (int i = tid; i < (KCHUNK / 4) * 8 / 4; i += THREADS) dst[i] = src[i];
    }

    const int* __restrict__ pA =
        W + (size_t)(rowbase + warp * 16 + g) * IN_F + kbase + 4 * t;
    const uint2* __restrict__ xbh =
        ((const uint2*)g_xbq) + (size_t)sbase * 128 + g * 4 + t;
    const uint2* __restrict__ xbl =
        ((const uint2*)g_xlq) + (size_t)sbase * 96 + g * 4 + t;

    int acch[4][4];                                     // hi, MMA frag layout
    int accli[3][4];                                    // lo IMMA, j=0..2
    int acclo[2][8];                                    // lo dp4a, k-partials
#pragma unroll
    for (int j = 0; j < 4; j++)
#pragma unroll
        for (int e = 0; e < 4; e++) acch[j][e] = 0;
#pragma unroll
    for (int j = 0; j < 3; j++)
#pragma unroll
        for (int e = 0; e < 4; e++) accli[j][e] = 0;
#pragma unroll
    for (int r = 0; r < 2; r++)
#pragma unroll
        for (int e = 0; e < 8; e++) acclo[r][e] = 0;

    int4 ca[4], na[4];
    uint2 cb[4], nb[4], cbl[3], nbl[3];

#define LOAD_A(dst, ko)                                                   \
    do {                                                                  \
        dst[0] = __ldcs((const int4*)(pA + (ko)));                        \
        dst[1] = __ldcs((const int4*)(pA + (size_t)8 * IN_F + (ko)));     \
        dst[2] = __ldcs((const int4*)(pA + (ko) + 16));                   \
        dst[3] = __ldcs((const int4*)(pA + (size_t)8 * IN_F + (ko) + 16));\
    } while (0)

#define LOAD_B(dst, dstl, fs_)                                            \
    do {                                                                  \
        const uint2* _p = xbh + (size_t)(fs_) * 128;                      \
        _Pragma("unroll")                                                 \
        for (int j = 0; j < 4; j++) dst[j] = _p[j * 32];                  \
        const uint2* _q = xbl + (size_t)(fs_) * 96;                       \
        _Pragma("unroll")                                                 \
        for (int j = 0; j < 3; j++) dstl[j] = _q[j * 32];                 \
    } while (0)

    LOAD_A(ca, 0);
    LOAD_B(cb, cbl, 0);
    __syncthreads();

#pragma unroll 2
    for (int it = 0; it < NIT; ++it) {
        if (it + 1 < NIT) {
            LOAD_A(na, (it + 1) * 32);
            LOAD_B(nb, nbl, it + 1);
        }

        uint32_t A0 = pack_s8(ca[0]);
        uint32_t A1 = pack_s8(ca[1]);
        uint32_t A2 = pack_s8(ca[2]);
        uint32_t A3 = pack_s8(ca[3]);

        // tensor pipe: hi (4) + lo b<24 (3)
#pragma unroll
        for (int j = 0; j < 4; j++)
            imma16832(acch[j], A0, A1, A2, A3, cb[j].x, cb[j].y);
#pragma unroll
        for (int j = 0; j < 3; j++)
            imma16832(accli[j], A0, A1, A2, A3, cbl[j].x, cbl[j].y);

        // dp4a pipe: lo b=24..31 with OWN weights (k-ownership, no shuffles).
        // Thread covers k4 groups {8it+t, 8it+t+4}; quad-reduce at the end.
        uint32_t xa[8], xc[8];
        {
            const uint32_t* xr = sxlo + ((it * 8 + t) << 3);
            *(uint4*)&xa[0] = *(const uint4*)(xr);
            *(uint4*)&xa[4] = *(const uint4*)(xr + 4);
            *(uint4*)&xc[0] = *(const uint4*)(xr + 32);
            *(uint4*)&xc[4] = *(const uint4*)(xr + 36);
        }
#pragma unroll
        for (int j = 0; j < 8; j++) {
            acclo[0][j] = dp4a_(A0, xa[j], acclo[0][j]);
            acclo[0][j] = dp4a_(A2, xc[j], acclo[0][j]);
            acclo[1][j] = dp4a_(A1, xa[j], acclo[1][j]);
            acclo[1][j] = dp4a_(A3, xc[j], acclo[1][j]);
        }

#pragma unroll
        for (int q2 = 0; q2 < 4; q2++) ca[q2] = na[q2];
#pragma unroll
        for (int j = 0; j < 4; j++) cb[j] = nb[j];
#pragma unroll
        for (int j = 0; j < 3; j++) cbl[j] = nbl[j];
    }

    // One-time quad reduction of dp4a k-partials (lanes t=0..3 of each g).
#pragma unroll
    for (int r = 0; r < 2; r++)
#pragma unroll
        for (int j = 0; j < 8; j++) {
            int v = acclo[r][j];
            v += __shfl_xor_sync(0xffffffffu, v, 1);
            v += __shfl_xor_sync(0xffffffffu, v, 2);
            acclo[r][j] = v;
        }

    // Combine hi+lo in-register; write f32 partials (streaming).
    float* pk = g_partial + (size_t)blockIdx.y * OUT_F * BATCH;
    const int rg = rowbase + warp * 16 + g;
#pragma unroll
    for (int j = 0; j < 4; j++) {
        const int n0 = 8 * j + 2 * t;
        float2 v0, v1;
        if (j < 3) {
            v0.x = S0 * (float)acch[j][0] + S1 * (float)accli[j][0];
            v0.y = S0 * (float)acch[j][1] + S1 * (float)accli[j][1];
            v1.x = S0 * (float)acch[j][2] + S1 * (float)accli[j][2];
            v1.y = S0 * (float)acch[j][3] + S1 * (float)accli[j][3];
        } else {
            v0.x = S0 * (float)acch[j][0] + S1 * (float)acclo[0][2 * t];
            v0.y = S0 * (float)acch[j][1] + S1 * (float)acclo[0][2 * t + 1];
            v1.x = S0 * (float)acch[j][2] + S1 * (float)acclo[1][2 * t];
            v1.y = S0 * (float)acch[j][3] + S1 * (float)acclo[1][2 * t + 1];
        }
        __stcs((float2*)(pk + (size_t)rg * BATCH + n0), v0);
        __stcs((float2*)(pk + (size_t)(rg + 8) * BATCH + n0), v1);
    }

    // Tail-block finalize: last CTA of this m-tile reduces across ky.
    __shared__ int sflag;
    __threadfence();
    if (tid == 0) {
        int old = atomicAdd(&g_cnt[mt], 1);
        sflag = (old == KSPLIT - 1);
    }
    __syncthreads();
    if (!sflag) return;

    const float4* __restrict__ base = (const float4*)g_partial;
#pragma unroll
    for (int q2 = 0; q2 < 4; q2++) {
        int task = tid + THREADS * q2;                  // 512: 64 rows x 8 bq
        int row  = task >> 3;
        int bq   = task & 7;
        int o    = rowbase + row;

        float4 s = make_float4(0.f, 0.f, 0.f, 0.f);
#pragma unroll
        for (int ky = 0; ky < KSPLIT; ky++) {
            float4 p = __ldcs(&base[((size_t)ky * OUT_F + o) * (BATCH / 4) + bq]);
            s.x += p.x; s.y += p.y; s.z += p.z; s.w += p.w;
        }

        float ls = log_scale[o];
        float sp = (ls > 20.0f) ? ls : log1pf(expf(ls));
        float sc = fmaxf(sp, 1e-4f);
        float bi = bias[o];

        int b0 = bq << 2;
        out[(size_t)(b0 + 0) * OUT_F + o] = fmaf(sc, s.x, bi);
        out[(size_t)(b0 + 1) * OUT_F + o] = fmaf(sc, s.y, bi);
        out[(size_t)(b0 + 2) * OUT_F + o] = fmaf(sc, s.z, bi);
        out[(size_t)(b0 + 3) * OUT_F + o] = fmaf(sc, s.w, bi);
    }
}

// ---- Launch ------------------------------------------------------------------
extern "C" void kernel_launch(void* const* d_in, const int* in_sizes, int n_in,
                              void* d_out, int out_size) {
    const float* x  = nullptr;
    const int*   W  = nullptr;
    const float* ls = nullptr;
    const float* bi = nullptr;
    for (int i = 0; i < n_in; i++) {
        long long sz = in_sizes[i];
        if (sz == (long long)OUT_F * IN_F)      W = (const int*)d_in[i];
        else if (sz == (long long)BATCH * IN_F) x = (const float*)d_in[i];
        else if (sz == OUT_F) {
            if (!ls) ls = (const float*)d_in[i];
            else     bi = (const float*)d_in[i];
        }
    }
    float* out = (float*)d_out;

    xprep_kernel<<<(BATCH * IN_F / 4) / 128, 128>>>(x);

    dim3 grid(NMT, KSPLIT);                      // (128, 8) = 1024 CTAs
    gemm_kernel<<<grid, THREADS>>>(W, ls, bi, out);
}